// round 9
// baseline (speedup 1.0000x reference)
#include <cuda_runtime.h>
#include <cstdint>

#define BB 16
#define NN 16
#define HH 512
#define WW 512
#define HW (HH*WW)            // 262144 floats per plane
#define Q4 (HW/4)             // 65536 float4 per plane
#define TILE_F4 1024          // float4 per tile -> 16 KB smem = 8 full rows
#define TILE_ROWS 8
#define NCHUNK (Q4/TILE_F4)   // 64 chunks per plane
#define THREADS 256
#define ITERS (TILE_F4/THREADS)  // 4
#define NBLOCKS (NCHUNK*BB)   // 1024

// Deterministic per-chunk partials; every slot written on every launch.
__device__ float g_part_ov[BB*NN*NCHUNK];   // overlap partials
__device__ float g_part_in[BB*NN*NCHUNK];   // box-intersection partials
__device__ float g_part_ta[BB*NCHUNK];      // target-area partials
__device__ unsigned int g_done;             // 0 at load; last block resets it

__device__ __forceinline__ float warp_sum(float v) {
    #pragma unroll
    for (int off = 16; off > 0; off >>= 1)
        v += __shfl_xor_sync(0xffffffff, v, off);
    return v;
}

// grid: (NCHUNK, BB). Stage one 8-row target tile in smem, stream all 16
// mask planes against it (DRAM-bound), compute per-box intersection
// partials from the smem tile; the LAST block folds everything.
// launch_bounds(256,5): cap regs at 52 so >=5 CTAs/SM keep DRAM saturated.
__global__ __launch_bounds__(THREADS, 5)
void overlap_kernel(const float4* __restrict__ masks,
                    const float4* __restrict__ target,
                    const int4*   __restrict__ boxes,
                    float*        __restrict__ out) {
    __shared__ float4 s_t[TILE_F4];            // 16 KB: 8 rows x 128 float4
    __shared__ float  s_red[NN * (THREADS/32)];
    __shared__ float  s_ta[THREADS/32];
    __shared__ bool   s_last;

    const int b     = blockIdx.y;
    const int chunk = blockIdx.x;
    const int tid   = threadIdx.x;
    const int lane  = tid & 31;
    const int wid   = tid >> 5;

    // --- load target tile into smem + accumulate its sum (target_area) ---
    const float4* t = target + (size_t)b * Q4 + (size_t)chunk * TILE_F4;
    float tac = 0.0f;
    #pragma unroll
    for (int k = 0; k < ITERS; k++) {
        const int i = tid + k * THREADS;
        float4 v = t[i];
        s_t[i] = v;
        tac += v.x + v.y + v.z + v.w;
    }
    tac = warp_sum(tac);
    if (lane == 0) s_ta[wid] = tac;
    __syncthreads();

    // --- stream the 16 mask planes against the smem tile ---
    const float4* mbase = masks + ((size_t)b * NN) * Q4 + (size_t)chunk * TILE_F4;
    float acc[NN];
    #pragma unroll
    for (int n = 0; n < NN; n++) {
        const float4* m = mbase + (size_t)n * Q4;
        float a0 = 0.0f;
        #pragma unroll
        for (int k = 0; k < ITERS; k++) {
            const int i = tid + k * THREADS;
            float4 a = m[i];
            float4 c = s_t[i];
            a0 += a.x*c.x + a.y*c.y + a.z*c.z + a.w*c.w;
        }
        acc[n] = a0;
    }
    #pragma unroll
    for (int n = 0; n < NN; n++) {
        acc[n] = warp_sum(acc[n]);
        if (lane == 0) s_red[n * (THREADS/32) + wid] = acc[n];
    }

    // --- box-intersection partials from the smem tile, LDS.128 middle +
    //     scalar head/tail. Warp w handles boxes w and w+8. ---
    {
        const float* tf = (const float*)s_t;       // 8 rows x 512 floats
        const int row0  = chunk * TILE_ROWS;
        #pragma unroll
        for (int pass = 0; pass < 2; pass++) {
            const int nb = wid + pass * 8;
            const int4 bx = boxes[b * NN + nb];    // x1,y1,x2,y2
            const int rlo = max(bx.y - row0, 0);
            const int rhi = min(bx.w - row0, TILE_ROWS);
            const int a0 = (bx.x + 3) & ~3;        // first 16B-aligned col
            const int a1 = bx.z & ~3;              // end of aligned region
            float s = 0.0f;
            if (a1 <= a0) {                        // narrow box: pure scalar
                for (int r = rlo; r < rhi; r++) {
                    const float* row = tf + r * WW;
                    for (int c = bx.x + lane; c < bx.z; c += 32)
                        s += row[c];
                }
            } else {
                const int n4 = (a1 - a0) >> 2;
                for (int r = rlo; r < rhi; r++) {
                    const float* row = tf + r * WW;
                    if (lane < a0 - bx.x) s += row[bx.x + lane];   // head <=3
                    if (lane < bx.z - a1) s += row[a1 + lane];     // tail <=3
                    const float4* r4 = (const float4*)(row + a0);
                    for (int i = lane; i < n4; i += 32) {
                        float4 v = r4[i];
                        s += (v.x + v.y) + (v.z + v.w);
                    }
                }
            }
            s = warp_sum(s);
            if (lane == 0)
                g_part_in[((size_t)b * NN + nb) * NCHUNK + chunk] = s;
        }
    }
    __syncthreads();

    // --- write remaining per-chunk partials ---
    if (tid < NN) {
        float s = 0.0f;
        #pragma unroll
        for (int w = 0; w < THREADS/32; w++) s += s_red[tid * (THREADS/32) + w];
        g_part_ov[((size_t)b * NN + tid) * NCHUNK + chunk] = s;
    }
    if (tid == NN) {
        float s = 0.0f;
        #pragma unroll
        for (int w = 0; w < THREADS/32; w++) s += s_ta[w];
        g_part_ta[b * NCHUNK + chunk] = s;
    }

    // --- completion protocol: make partials visible, count this block ---
    __threadfence();
    __syncthreads();
    if (tid == 0) {
        unsigned int ticket = atomicAdd(&g_done, 1u);
        s_last = (ticket == NBLOCKS - 1);
        if (s_last) g_done = 0;                // deterministic across replays
    }
    __syncthreads();
    if (!s_last) return;

    // --- last block folds everything: warp w handles bn in [w*32, w*32+32).
    //     lane == chunk (coalesced); __ldcg bypasses L1 (other SMs wrote).
    //     unroll 1: keep this cold path from inflating peak register use. ---
    {
        float taA = __ldcg(&g_part_ta[(2*wid)   * NCHUNK + lane])
                  + __ldcg(&g_part_ta[(2*wid)   * NCHUNK + lane + 32]);
        float taB = __ldcg(&g_part_ta[(2*wid+1) * NCHUNK + lane])
                  + __ldcg(&g_part_ta[(2*wid+1) * NCHUNK + lane + 32]);
        taA = warp_sum(taA);
        taB = warp_sum(taB);

        #pragma unroll 1
        for (int j = 0; j < 32; j++) {
            const int bn = wid * 32 + j;
            float ov = __ldcg(&g_part_ov[(size_t)bn * NCHUNK + lane])
                     + __ldcg(&g_part_ov[(size_t)bn * NCHUNK + lane + 32]);
            float in = __ldcg(&g_part_in[(size_t)bn * NCHUNK + lane])
                     + __ldcg(&g_part_in[(size_t)bn * NCHUNK + lane + 32]);
            ov = warp_sum(ov);
            in = warp_sum(in);
            if (lane == 0) {
                const int4 bx = boxes[bn];
                const float box_area = (float)(bx.z - bx.x) * (float)(bx.w - bx.y);
                const float ta = (j < 16) ? taA : taB;
                const float uni = box_area + ta - in;
                out[bn*2 + 0] = ov;
                out[bn*2 + 1] = in / (uni + 1e-8f);
            }
        }
    }
}

extern "C" void kernel_launch(void* const* d_in, const int* in_sizes, int n_in,
                              void* d_out, int out_size) {
    const float* masks  = (const float*)d_in[0];
    const float* target = (const float*)d_in[1];
    const int4*  boxes  = (const int4*)d_in[2];
    float* out = (float*)d_out;

    dim3 grid(NCHUNK, BB);
    overlap_kernel<<<grid, THREADS>>>((const float4*)masks,
                                      (const float4*)target, boxes, out);
}

// round 10
// speedup vs baseline: 1.2015x; 1.2015x over previous
#include <cuda_runtime.h>
#include <cstdint>

#define BB 16
#define NN 16
#define HH 512
#define WW 512
#define HW (HH*WW)            // 262144 floats per plane
#define Q4 (HW/4)             // 65536 float4 per plane
#define TILE_F4 1024          // float4 per tile -> 16 KB smem = 8 full rows
#define TILE_ROWS 8
#define NCHUNK (Q4/TILE_F4)   // 64 chunks per plane
#define THREADS 256
#define ITERS (TILE_F4/THREADS)  // 4

// Deterministic per-chunk partials; every slot written on every launch,
// so no zero-init and no atomics are needed.
__device__ float g_part_ov[BB*NN*NCHUNK];   // overlap partials
__device__ float g_part_in[BB*NN*NCHUNK];   // box-intersection partials
__device__ float g_part_ta[BB*NCHUNK];      // target-area partials

__device__ __forceinline__ float warp_sum(float v) {
    #pragma unroll
    for (int off = 16; off > 0; off >>= 1)
        v += __shfl_xor_sync(0xffffffff, v, off);
    return v;
}

// grid: (NCHUNK, BB). Stage one 8-row target tile in smem, stream all 16
// mask planes against it. k-outer / n-inner with explicit 8-wide load
// batches: 8 independent LDG.128 in flight per group (high MLP), and the
// smem tile value is reused 16x per load.
__global__ __launch_bounds__(THREADS)
void overlap_kernel(const float4* __restrict__ masks,
                    const float4* __restrict__ target,
                    const int4*   __restrict__ boxes) {
    __shared__ float4 s_t[TILE_F4];            // 16 KB: 8 rows x 128 float4
    __shared__ float  s_red[NN * (THREADS/32)];
    __shared__ float  s_ta[THREADS/32];

    const int b     = blockIdx.y;
    const int chunk = blockIdx.x;
    const int tid   = threadIdx.x;
    const int lane  = tid & 31;
    const int wid   = tid >> 5;

    // --- load target tile into smem + accumulate its sum (target_area) ---
    const float4* t = target + (size_t)b * Q4 + (size_t)chunk * TILE_F4;
    float tac = 0.0f;
    #pragma unroll
    for (int k = 0; k < ITERS; k++) {
        const int i = tid + k * THREADS;
        float4 v = t[i];
        s_t[i] = v;
        tac += v.x + v.y + v.z + v.w;
    }
    tac = warp_sum(tac);
    if (lane == 0) s_ta[wid] = tac;
    __syncthreads();

    // --- stream the 16 mask planes, k-outer / n-inner, 8-wide batches ---
    const float4* mbase = masks + ((size_t)b * NN) * Q4 + (size_t)chunk * TILE_F4;
    float acc[NN];
    #pragma unroll
    for (int n = 0; n < NN; n++) acc[n] = 0.0f;

    #pragma unroll
    for (int k = 0; k < ITERS; k++) {
        const int i = tid + k * THREADS;
        const float4 c = s_t[i];
        #pragma unroll
        for (int g = 0; g < 2; g++) {
            float4 v[8];
            #pragma unroll
            for (int j = 0; j < 8; j++)
                v[j] = mbase[(size_t)(g*8 + j) * Q4 + i];   // 8 independent LDG.128
            #pragma unroll
            for (int j = 0; j < 8; j++)
                acc[g*8 + j] += v[j].x*c.x + v[j].y*c.y + v[j].z*c.z + v[j].w*c.w;
        }
    }
    #pragma unroll
    for (int n = 0; n < NN; n++) {
        acc[n] = warp_sum(acc[n]);
        if (lane == 0) s_red[n * (THREADS/32) + wid] = acc[n];
    }

    // --- box-intersection partials from the smem tile, LDS.128 middle +
    //     scalar head/tail. Warp w handles boxes w and w+8. ---
    {
        const float* tf = (const float*)s_t;       // 8 rows x 512 floats
        const int row0  = chunk * TILE_ROWS;
        #pragma unroll
        for (int pass = 0; pass < 2; pass++) {
            const int nb = wid + pass * 8;
            const int4 bx = boxes[b * NN + nb];    // x1,y1,x2,y2
            const int rlo = max(bx.y - row0, 0);
            const int rhi = min(bx.w - row0, TILE_ROWS);
            const int a0 = (bx.x + 3) & ~3;        // first 16B-aligned col
            const int a1 = bx.z & ~3;              // end of aligned region
            float s = 0.0f;
            if (a1 <= a0) {                        // narrow box: pure scalar
                for (int r = rlo; r < rhi; r++) {
                    const float* row = tf + r * WW;
                    for (int c = bx.x + lane; c < bx.z; c += 32)
                        s += row[c];
                }
            } else {
                const int n4 = (a1 - a0) >> 2;
                for (int r = rlo; r < rhi; r++) {
                    const float* row = tf + r * WW;
                    if (lane < a0 - bx.x) s += row[bx.x + lane];   // head <=3
                    if (lane < bx.z - a1) s += row[a1 + lane];     // tail <=3
                    const float4* r4 = (const float4*)(row + a0);
                    for (int i = lane; i < n4; i += 32) {
                        float4 v = r4[i];
                        s += (v.x + v.y) + (v.z + v.w);
                    }
                }
            }
            s = warp_sum(s);
            if (lane == 0)
                g_part_in[((size_t)b * NN + nb) * NCHUNK + chunk] = s;
        }
    }
    __syncthreads();

    // --- write remaining per-chunk partials ---
    if (tid < NN) {
        float s = 0.0f;
        #pragma unroll
        for (int w = 0; w < THREADS/32; w++) s += s_red[tid * (THREADS/32) + w];
        g_part_ov[((size_t)b * NN + tid) * NCHUNK + chunk] = s;
    }
    if (tid == NN) {
        float s = 0.0f;
        #pragma unroll
        for (int w = 0; w < THREADS/32; w++) s += s_ta[w];
        g_part_ta[b * NCHUNK + chunk] = s;
    }
}

// grid: 32 blocks x 8 warps; warp w of block g handles bn = g*8 + w.
// Each lane folds chunks (lane) and (lane+32).
__global__ __launch_bounds__(THREADS)
void finalize_kernel(const int4* __restrict__ boxes,
                     float* __restrict__ out) {
    const int wid  = threadIdx.x >> 5;
    const int lane = threadIdx.x & 31;
    const int bn   = blockIdx.x * 8 + wid;
    const int b    = bn >> 4;

    float ov = g_part_ov[(size_t)bn * NCHUNK + lane]
             + g_part_ov[(size_t)bn * NCHUNK + lane + 32];
    float in = g_part_in[(size_t)bn * NCHUNK + lane]
             + g_part_in[(size_t)bn * NCHUNK + lane + 32];
    float ta = g_part_ta[b * NCHUNK + lane]
             + g_part_ta[b * NCHUNK + lane + 32];
    ov = warp_sum(ov);
    in = warp_sum(in);
    ta = warp_sum(ta);

    if (lane == 0) {
        const int4 bx = boxes[bn];
        const float box_area = (float)(bx.z - bx.x) * (float)(bx.w - bx.y);
        const float uni = box_area + ta - in;
        out[bn*2 + 0] = ov;
        out[bn*2 + 1] = in / (uni + 1e-8f);
    }
}

extern "C" void kernel_launch(void* const* d_in, const int* in_sizes, int n_in,
                              void* d_out, int out_size) {
    const float* masks  = (const float*)d_in[0];
    const float* target = (const float*)d_in[1];
    const int4*  boxes  = (const int4*)d_in[2];
    float* out = (float*)d_out;

    dim3 grid(NCHUNK, BB);
    overlap_kernel<<<grid, THREADS>>>((const float4*)masks,
                                      (const float4*)target, boxes);
    finalize_kernel<<<32, THREADS>>>(boxes, out);
}

// round 14
// speedup vs baseline: 1.4360x; 1.1952x over previous
#include <cuda_runtime.h>
#include <cstdint>

#define BB 16
#define NN 16
#define HH 512
#define WW 512
#define HW (HH*WW)            // 262144 floats per plane
#define Q4 (HW/4)             // 65536 float4 per plane
#define TILE_F4 1024          // float4 per tile -> 16 KB smem = 8 full rows
#define TILE_ROWS 8
#define NCHUNK (Q4/TILE_F4)   // 64 chunks per plane
#define THREADS 256
#define ITERS (TILE_F4/THREADS)  // 4

// Deterministic per-chunk partials; every slot written on every launch,
// so no zero-init and no atomics are needed.
__device__ float g_part_ov[BB*NN*NCHUNK];   // overlap partials
__device__ float g_part_in[BB*NN*NCHUNK];   // box-intersection partials
__device__ float g_part_ta[BB*NCHUNK];      // target-area partials

__device__ __forceinline__ float warp_sum(float v) {
    #pragma unroll
    for (int off = 16; off > 0; off >>= 1)
        v += __shfl_xor_sync(0xffffffff, v, off);
    return v;
}

// grid: (NCHUNK, BB). Stage one 8-row target tile in smem, stream all 16
// mask planes against it. n-outer like the 53.2us version, but planes are
// processed in PAIRS: 8 independent LDG.128 front-batched per iteration
// (2 streams per warp only -> DRAM-locality preserved).
__global__ __launch_bounds__(THREADS)
void overlap_kernel(const float4* __restrict__ masks,
                    const float4* __restrict__ target,
                    const int4*   __restrict__ boxes) {
    __shared__ float4 s_t[TILE_F4];            // 16 KB: 8 rows x 128 float4
    __shared__ float  s_red[NN * (THREADS/32)];
    __shared__ float  s_ta[THREADS/32];

    const int b     = blockIdx.y;
    const int chunk = blockIdx.x;
    const int tid   = threadIdx.x;
    const int lane  = tid & 31;
    const int wid   = tid >> 5;

    // --- load target tile into smem + accumulate its sum (target_area) ---
    const float4* t = target + (size_t)b * Q4 + (size_t)chunk * TILE_F4;
    float tac = 0.0f;
    #pragma unroll
    for (int k = 0; k < ITERS; k++) {
        const int i = tid + k * THREADS;
        float4 v = t[i];
        s_t[i] = v;
        tac += v.x + v.y + v.z + v.w;
    }
    tac = warp_sum(tac);
    if (lane == 0) s_ta[wid] = tac;
    __syncthreads();

    // --- stream the 16 mask planes in pairs against the smem tile ---
    const float4* mbase = masks + ((size_t)b * NN) * Q4 + (size_t)chunk * TILE_F4;
    float acc[NN];
    #pragma unroll
    for (int n = 0; n < NN; n += 2) {
        const float4* m0 = mbase + (size_t)n * Q4;
        const float4* m1 = m0 + Q4;
        // front-batch all 8 independent LDG.128 for this plane pair
        float4 v0[ITERS], v1[ITERS];
        #pragma unroll
        for (int k = 0; k < ITERS; k++) {
            const int i = tid + k * THREADS;
            v0[k] = m0[i];
            v1[k] = m1[i];
        }
        float a0 = 0.0f, a1 = 0.0f;
        #pragma unroll
        for (int k = 0; k < ITERS; k++) {
            const int i = tid + k * THREADS;
            const float4 c = s_t[i];
            a0 += v0[k].x*c.x + v0[k].y*c.y + v0[k].z*c.z + v0[k].w*c.w;
            a1 += v1[k].x*c.x + v1[k].y*c.y + v1[k].z*c.z + v1[k].w*c.w;
        }
        acc[n]   = a0;
        acc[n+1] = a1;
    }
    #pragma unroll
    for (int n = 0; n < NN; n++) {
        acc[n] = warp_sum(acc[n]);
        if (lane == 0) s_red[n * (THREADS/32) + wid] = acc[n];
    }

    // --- box-intersection partials from the smem tile, LDS.128 middle +
    //     scalar head/tail. Warp w handles boxes w and w+8. ---
    {
        const float* tf = (const float*)s_t;       // 8 rows x 512 floats
        const int row0  = chunk * TILE_ROWS;
        #pragma unroll
        for (int pass = 0; pass < 2; pass++) {
            const int nb = wid + pass * 8;
            const int4 bx = boxes[b * NN + nb];    // x1,y1,x2,y2
            const int rlo = max(bx.y - row0, 0);
            const int rhi = min(bx.w - row0, TILE_ROWS);
            const int a0 = (bx.x + 3) & ~3;        // first 16B-aligned col
            const int a1 = bx.z & ~3;              // end of aligned region
            float s = 0.0f;
            if (a1 <= a0) {                        // narrow box: pure scalar
                for (int r = rlo; r < rhi; r++) {
                    const float* row = tf + r * WW;
                    for (int c = bx.x + lane; c < bx.z; c += 32)
                        s += row[c];
                }
            } else {
                const int n4 = (a1 - a0) >> 2;
                for (int r = rlo; r < rhi; r++) {
                    const float* row = tf + r * WW;
                    if (lane < a0 - bx.x) s += row[bx.x + lane];   // head <=3
                    if (lane < bx.z - a1) s += row[a1 + lane];     // tail <=3
                    const float4* r4 = (const float4*)(row + a0);
                    for (int i = lane; i < n4; i += 32) {
                        float4 v = r4[i];
                        s += (v.x + v.y) + (v.z + v.w);
                    }
                }
            }
            s = warp_sum(s);
            if (lane == 0)
                g_part_in[((size_t)b * NN + nb) * NCHUNK + chunk] = s;
        }
    }
    __syncthreads();

    // --- write remaining per-chunk partials ---
    if (tid < NN) {
        float s = 0.0f;
        #pragma unroll
        for (int w = 0; w < THREADS/32; w++) s += s_red[tid * (THREADS/32) + w];
        g_part_ov[((size_t)b * NN + tid) * NCHUNK + chunk] = s;
    }
    if (tid == NN) {
        float s = 0.0f;
        #pragma unroll
        for (int w = 0; w < THREADS/32; w++) s += s_ta[w];
        g_part_ta[b * NCHUNK + chunk] = s;
    }
}

// grid: 32 blocks x 8 warps; warp w of block g handles bn = g*8 + w.
// Each lane folds chunks (lane) and (lane+32).
__global__ __launch_bounds__(THREADS)
void finalize_kernel(const int4* __restrict__ boxes,
                     float* __restrict__ out) {
    const int wid  = threadIdx.x >> 5;
    const int lane = threadIdx.x & 31;
    const int bn   = blockIdx.x * 8 + wid;
    const int b    = bn >> 4;

    float ov = g_part_ov[(size_t)bn * NCHUNK + lane]
             + g_part_ov[(size_t)bn * NCHUNK + lane + 32];
    float in = g_part_in[(size_t)bn * NCHUNK + lane]
             + g_part_in[(size_t)bn * NCHUNK + lane + 32];
    float ta = g_part_ta[b * NCHUNK + lane]
             + g_part_ta[b * NCHUNK + lane + 32];
    ov = warp_sum(ov);
    in = warp_sum(in);
    ta = warp_sum(ta);

    if (lane == 0) {
        const int4 bx = boxes[bn];
        const float box_area = (float)(bx.z - bx.x) * (float)(bx.w - bx.y);
        const float uni = box_area + ta - in;
        out[bn*2 + 0] = ov;
        out[bn*2 + 1] = in / (uni + 1e-8f);
    }
}

extern "C" void kernel_launch(void* const* d_in, const int* in_sizes, int n_in,
                              void* d_out, int out_size) {
    const float* masks  = (const float*)d_in[0];
    const float* target = (const float*)d_in[1];
    const int4*  boxes  = (const int4*)d_in[2];
    float* out = (float*)d_out;

    dim3 grid(NCHUNK, BB);
    overlap_kernel<<<grid, THREADS>>>((const float4*)masks,
                                      (const float4*)target, boxes);
    finalize_kernel<<<32, THREADS>>>(boxes, out);
}